// round 13
// baseline (speedup 1.0000x reference)
#include <cuda_runtime.h>
#include <math.h>

// ---------------- problem constants ----------------
#define DD     128          // feature dim
#define NCLS   32           // number of classes
#define OCHUNK 1024         // rows per hist/order chunk
#define GCHUNK 896          // rows per gemm CTA (multiple of BATCH)
#define MAXCHUNK 1024
#define GTPB   288          // gemm threads per block (9 warps)
#define BATCH  32           // rows staged per smem batch
#define MAXM   (1 << 19)

// cholesky kernel config
#define CTPB   512
#define NPAIRS ((DD * (DD - 1)) / 2)   // 8128 strictly-lower elements
#define PPT    16                      // pairs per thread

// ---------------- device scratch ----------------
__device__ float  g_cov[NCLS + 1][DD][DD];      // [32] = global (dual-atomic flush)
__device__ int    g_chunk_cnt[MAXCHUNK][NCLS];
__device__ int    g_counts[NCLS];
__device__ int    g_class_start[NCLS + 1];
__device__ int    g_order[MAXM];
__device__ double g_logdet[NCLS + 1];
__device__ unsigned int g_done_h;               // self-resetting via atomicInc wrap
__device__ unsigned int g_done_c;

// ------- K1: per-chunk histogram + zero cov; LAST CTA runs the scan ----------
__global__ void k_hist(const int* __restrict__ label, int M, int nchunk) {
    __shared__ int cnt[NCLS];
    __shared__ int s_last;
    int tid = threadIdx.x, b = blockIdx.x;
    if (tid < NCLS) cnt[tid] = 0;
    __syncthreads();
    int base = b * OCHUNK;
    int end  = min(base + OCHUNK, M);
    for (int r = base + tid; r < end; r += blockDim.x)
        atomicAdd(&cnt[label[r]], 1);
    __syncthreads();
    if (tid < NCLS) g_chunk_cnt[b][tid] = cnt[tid];

    float* cf = &g_cov[0][0][0];
    const int TOT = (NCLS + 1) * DD * DD;
    for (int i = b * blockDim.x + tid; i < TOT; i += gridDim.x * blockDim.x)
        cf[i] = 0.0f;

    // last-done CTA performs the (proven serial) scan
    __threadfence();
    if (tid == 0)
        s_last = (atomicInc(&g_done_h, (unsigned)(nchunk - 1)) == (unsigned)(nchunk - 1)) ? 1 : 0;
    __syncthreads();
    if (s_last) {
        int j = tid;
        if (j < NCLS) {
            int tot = 0;
            for (int c = 0; c < nchunk; c++) tot += __ldcg(&g_chunk_cnt[c][j]);
            g_counts[j] = tot;
        }
        __syncthreads();
        if (j == 0) {
            int s = 0;
            for (int jj = 0; jj < NCLS; jj++) { g_class_start[jj] = s; s += g_counts[jj]; }
            g_class_start[NCLS] = s;
        }
        __syncthreads();
        if (j < NCLS) {
            int s = g_class_start[j];
            for (int c = 0; c < nchunk; c++) {
                int v = __ldcg(&g_chunk_cnt[c][j]);
                g_chunk_cnt[c][j] = s;
                s += v;
            }
        }
    }
}

// ---------------- K2: stable class-sorted order (proven) --------------------
__global__ void k_order(const int* __restrict__ label, int M) {
    __shared__ int lbl[OCHUNK];
    int tid = threadIdx.x, b = blockIdx.x;
    int base = b * OCHUNK;
    int n = min(OCHUNK, M - base);
    for (int i = tid; i < n; i += blockDim.x) lbl[i] = label[base + i];
    __syncthreads();
    if (tid < NCLS) {
        int pos = g_chunk_cnt[b][tid];
        for (int r = 0; r < n; r++)
            if (lbl[r] == tid) {
                if (pos >= 0 && pos < MAXM) g_order[pos] = base + r;
                pos++;
            }
    }
}

// ---------------- K3: segmented A^T A (R9 body, BATCH 32, dual flush) --------
typedef unsigned long long u64t;

__device__ __forceinline__ void accum_row2(const float* __restrict__ row,
                                           int ti, int tj, u64t acc[8][4]) {
    float4 a0 = *(const float4*)(row + (ti << 3));
    float4 a1 = *(const float4*)(row + (ti << 3) + 4);
    ulonglong2 bq0 = *(const ulonglong2*)(row + (tj << 3));
    ulonglong2 bq1 = *(const ulonglong2*)(row + (tj << 3) + 4);
    u64t bp[4] = {bq0.x, bq0.y, bq1.x, bq1.y};
    float av[8] = {a0.x, a0.y, a0.z, a0.w, a1.x, a1.y, a1.z, a1.w};
#pragma unroll
    for (int a = 0; a < 8; a++) {
        u64t ad;
        asm("mov.b64 %0, {%1, %1};" : "=l"(ad) : "f"(av[a]));
#pragma unroll
        for (int b = 0; b < 4; b++)
            asm("fma.rn.f32x2 %0, %1, %2, %0;" : "+l"(acc[a][b]) : "l"(ad), "l"(bp[b]));
    }
}

__device__ __forceinline__ void flush_acc2(int cls, int ti, int tj, u64t acc[8][4]) {
#pragma unroll
    for (int a = 0; a < 8; a++)
#pragma unroll
        for (int b = 0; b < 4; b++) {
            float lo, hi;
            asm("mov.b64 {%0, %1}, %2;" : "=f"(lo), "=f"(hi) : "l"(acc[a][b]));
            int r = ti * 8 + a, c = tj * 8 + 2 * b;
            atomicAdd(&g_cov[cls][r][c],      lo);
            atomicAdd(&g_cov[NCLS][r][c],     lo);
            atomicAdd(&g_cov[cls][r][c + 1],  hi);
            atomicAdd(&g_cov[NCLS][r][c + 1], hi);
            acc[a][b] = 0ull;
        }
}

__global__ void __launch_bounds__(GTPB, 2) k_gemm(const float* __restrict__ Z, int M) {
    __shared__ float s_rows[2][BATCH][DD];   // 32 KB, double buffered
    int tid = threadIdx.x;
    int wid = tid >> 5, lane = tid & 31;
    int p0 = blockIdx.x * GCHUNK;
    if (p0 >= M) return;
    int pend = min(p0 + GCHUNK, M);

    int grp = (tid >= 144) ? 1 : 0;
    int id  = tid - grp * 144;
    int ti = -1, tj = -1;
    if (id < 136) {
        int i = 0, rem = id;
        while (rem >= 16 - i) { rem -= 16 - i; i++; }
        ti = i; tj = i + rem;
    }

    u64t acc[8][4];
#pragma unroll
    for (int a = 0; a < 8; a++)
#pragma unroll
        for (int b = 0; b < 4; b++) acc[a][b] = 0ull;

    int cur = 0;
    while (cur < NCLS - 1 && g_class_start[cur + 1] <= p0) cur++;
    int nextb = g_class_start[cur + 1];

    // staging: 16 half-warps (warps 0-7); half-warp h stages rows h and h+16
    int srow = 2 * wid + (lane >> 4);
    int scol = lane & 15;

    if (wid < 8) {
#pragma unroll
        for (int rr = 0; rr < 2; rr++) {
            int pos = p0 + srow + rr * 16;
            if (pos < pend) {
                int row = g_order[pos];
                const float4* src = (const float4*)(Z + (size_t)row * DD);
                float4* dst = (float4*)s_rows[0][srow + rr * 16];
                dst[scol]      = src[scol];
                dst[scol + 16] = src[scol + 16];
            }
        }
    }
    __syncthreads();

    int ib = 0;
    for (int p = p0; p < pend; p += BATCH, ib ^= 1) {
        int nb = min(BATCH, pend - p);
        if (wid < 8 && p + BATCH < pend) {
#pragma unroll
            for (int rr = 0; rr < 2; rr++) {
                int pos = p + BATCH + srow + rr * 16;
                if (pos < pend) {
                    int row = g_order[pos];
                    const float4* src = (const float4*)(Z + (size_t)row * DD);
                    float4* dst = (float4*)s_rows[ib ^ 1][srow + rr * 16];
                    dst[scol]      = src[scol];
                    dst[scol + 16] = src[scol + 16];
                }
            }
        }

        if (nb == BATCH && p + BATCH <= nextb) {
            if (ti >= 0) {
#pragma unroll
                for (int k = 0; k < BATCH; k += 2)
                    accum_row2(s_rows[ib][k + grp], ti, tj, acc);
            }
        } else {
            for (int k = 0; k < nb; k++) {
                if (p + k >= nextb && cur < NCLS - 1) {
                    if (ti >= 0) flush_acc2(cur, ti, tj, acc);
                    cur++;
                    while (cur < NCLS - 1 && g_class_start[cur + 1] <= p + k) cur++;
                    nextb = g_class_start[cur + 1];
                }
                if (ti >= 0 && (k & 1) == grp)
                    accum_row2(s_rows[ib][k], ti, tj, acc);
            }
        }
        __syncthreads();
    }
    if (ti >= 0) flush_acc2(cur, ti, tj, acc);
}

// ------- K4: fast Cholesky (R12-proven) + last-block finalize (R11-proven) ---
__global__ void __launch_bounds__(CTPB) k_chol_fin(float* __restrict__ out, int M) {
    __shared__ float  s_colraw[DD];
    __shared__ float  s_col[DD];
    __shared__ float  s_piv[2];
    __shared__ double s_diag[DD];
    __shared__ double s_red[DD];
    __shared__ int    s_last;
    int j = blockIdx.x;                   // 0..31 class, 32 global
    int tid = threadIdx.x;

    bool has = (j == NCLS) || (g_counts[j] > 0);

    if (has) {
        const float (*C)[DD] = g_cov[j];

        int   prc[PPT];
        float pv[PPT];
#pragma unroll
        for (int i = 0; i < PPT; i++) {
            int p = tid + CTPB * i;
            if (p < NPAIRS) {
                int r = (int)((1.0f + sqrtf(1.0f + 8.0f * (float)p)) * 0.5f);
                while (r * (r - 1) / 2 > p) r--;
                while ((r + 1) * r / 2 <= p) r++;
                int c = p - r * (r - 1) / 2;
                prc[i] = (r << 16) | c;
                pv[i]  = C[c][r];
            } else {
                prc[i] = (127 << 16) | 0;
                pv[i]  = 0.0f;
            }
        }

        double mydiag = 0.0;
        if (tid < DD) {
            s_colraw[tid] = C[0][tid];
            mydiag = (double)C[tid][tid];
            if (tid == 0) { s_piv[0] = (float)mydiag; s_diag[0] = mydiag; }
        }
        __syncthreads();

        for (int k = 0; k < DD; k++) {
            if (tid < DD && tid > k) {
                float inv = rsqrtf(s_piv[k & 1]);
                float lrk = s_colraw[tid] * inv;
                s_col[tid] = lrk;
                mydiag -= (double)lrk * (double)lrk;
                if (tid == k + 1) {
                    s_piv[(k + 1) & 1] = (float)mydiag;
                    s_diag[tid] = mydiag;
                }
            }
            __syncthreads();
#pragma unroll
            for (int i = 0; i < PPT; i++) {
                int c = prc[i] & 0xFFFF;
                if (c > k) {
                    int r = prc[i] >> 16;
                    pv[i] -= s_col[r] * s_col[c];
                    if (c == k + 1) s_colraw[r] = pv[i];
                }
            }
            __syncthreads();
        }

        if (tid < DD) s_red[tid] = log(s_diag[tid]);
        __syncthreads();
        for (int s = DD / 2; s > 0; s >>= 1) {
            if (tid < s) s_red[tid] += s_red[tid + s];
            __syncthreads();
        }
        if (tid == 0) g_logdet[j] = s_red[0];
    } else {
        if (tid == 0) g_logdet[j] = 0.0;
    }

    // last block to finish runs the finalize (proven R11 pattern)
    __syncthreads();
    __threadfence();
    if (tid == 0)
        s_last = (atomicInc(&g_done_c, (unsigned)NCLS) == (unsigned)NCLS) ? 1 : 0;
    __syncthreads();
    if (s_last && tid < 32) {
        double m = (double)M;
        double term = 0.0;
        if (tid < NCLS) {
            int mj = g_counts[tid];
            if (mj > 0) {
                double cj = (double)DD / ((double)mj * 0.01);
                double ld = __ldcg(&g_logdet[tid]);
                term = ((double)DD * log(cj) + ld) * (double)mj / (2.0 * m);
            }
        }
#pragma unroll
        for (int d = 16; d > 0; d >>= 1)
            term += __shfl_down_sync(0xFFFFFFFFu, term, d);
        if (tid == 0) {
            double c = (double)DD / (m * 0.01);
            double expd = ((double)DD * log(c) + __ldcg(&g_logdet[NCLS])) * 0.5;
            out[0] = (float)(term - expd);
        }
    }
}

// ---------------- launch ----------------
extern "C" void kernel_launch(void* const* d_in, const int* in_sizes, int n_in,
                              void* d_out, int out_size) {
    const float* Z     = (const float*)d_in[0];
    const int*   label = (const int*)d_in[1];
    int M = in_sizes[1];
    int nchunk = (M + OCHUNK - 1) / OCHUNK;
    int ggrid  = (M + GCHUNK - 1) / GCHUNK;

    k_hist<<<nchunk, 256>>>(label, M, nchunk);
    k_order<<<nchunk, 256>>>(label, M);
    k_gemm<<<ggrid, GTPB>>>(Z, M);
    k_chol_fin<<<NCLS + 1, CTPB>>>((float*)d_out, M);
}

// round 14
// speedup vs baseline: 1.1704x; 1.1704x over previous
#include <cuda_runtime.h>
#include <math.h>

// ---------------- problem constants ----------------
#define DD     128          // feature dim
#define NCLS   32           // number of classes
#define OCHUNK 1024         // rows per hist/order chunk
#define GCHUNK 896          // rows per gemm CTA (multiple of BATCH)
#define MAXCHUNK 1024
#define GTPB   288          // gemm threads per block (9 warps)
#define BATCH  16           // rows staged per smem batch
#define MAXM   (1 << 19)
#define SCAN_GROUPS 16      // supports nchunk <= 512

// cholesky kernel config
#define CTPB   512
#define NTILES 528          // 32*33/2 lower-triangular 4x4 tiles

// ---------------- device scratch ----------------
__device__ float  g_cov[NCLS + 1][DD][DD];      // [32] = global (k_sumglobal)
__device__ int    g_chunk_cnt[MAXCHUNK][NCLS];
__device__ int    g_counts[NCLS];
__device__ int    g_class_start[NCLS + 1];
__device__ int    g_order[MAXM];
__device__ double g_logdet[NCLS + 1];
__device__ unsigned int g_done_c;               // self-resetting via atomicInc wrap

// ---------------- K1: per-chunk histogram + zero cov (proven R12) ------------
__global__ void k_hist(const int* __restrict__ label, int M) {
    __shared__ int cnt[NCLS];
    int tid = threadIdx.x, b = blockIdx.x;
    if (tid < NCLS) cnt[tid] = 0;
    __syncthreads();
    int base = b * OCHUNK;
    int end  = min(base + OCHUNK, M);
    for (int r = base + tid; r < end; r += blockDim.x)
        atomicAdd(&cnt[label[r]], 1);
    __syncthreads();
    if (tid < NCLS) g_chunk_cnt[b][tid] = cnt[tid];

    float* cf = &g_cov[0][0][0];
    const int TOT = (NCLS + 1) * DD * DD;
    for (int i = b * blockDim.x + tid; i < TOT; i += gridDim.x * blockDim.x)
        cf[i] = 0.0f;
}

// ------- K2: parallel offsets (proven R12). Warp j = class j. ----------------
__global__ void k_scan(int nchunk) {
    __shared__ int s_tot[NCLS];
    __shared__ int s_start[NCLS + 1];
    int j = threadIdx.x >> 5;
    int l = threadIdx.x & 31;

    int c[SCAN_GROUPS], excl[SCAN_GROUPS];
    int run = 0;
#pragma unroll
    for (int i = 0; i < SCAN_GROUPS; i++) {
        int b = 32 * i + l;
        c[i] = (b < nchunk) ? g_chunk_cnt[b][j] : 0;
        int incl = c[i];
#pragma unroll
        for (int d = 1; d < 32; d <<= 1) {
            int v = __shfl_up_sync(0xFFFFFFFFu, incl, d);
            if (l >= d) incl += v;
        }
        excl[i] = run + (incl - c[i]);
        run += __shfl_sync(0xFFFFFFFFu, incl, 31);
    }
    if (l == 0) s_tot[j] = run;
    __syncthreads();
    if (threadIdx.x == 0) {
        int s = 0;
        for (int jj = 0; jj < NCLS; jj++) { s_start[jj] = s; s += s_tot[jj]; }
        s_start[NCLS] = s;
    }
    __syncthreads();
    if (l == 0) {
        g_counts[j] = s_tot[j];
        g_class_start[j] = s_start[j];
        if (j == 0) g_class_start[NCLS] = s_start[NCLS];
    }
    int base = s_start[j];
#pragma unroll
    for (int i = 0; i < SCAN_GROUPS; i++) {
        int b = 32 * i + l;
        if (b < nchunk) g_chunk_cnt[b][j] = base + excl[i];
    }
}

// ---------------- K3: stable class-sorted order (proven R12) -----------------
__global__ void k_order(const int* __restrict__ label, int M) {
    __shared__ int lbl[OCHUNK];
    int tid = threadIdx.x, b = blockIdx.x;
    int base = b * OCHUNK;
    int n = min(OCHUNK, M - base);
    for (int i = tid; i < n; i += blockDim.x) lbl[i] = label[base + i];
    __syncthreads();
    if (tid < NCLS) {
        int pos = g_chunk_cnt[b][tid];
        for (int r = 0; r < n; r++)
            if (lbl[r] == tid) {
                if (pos >= 0 && pos < MAXM) g_order[pos] = base + r;
                pos++;
            }
    }
}

// ---------------- K4: segmented A^T A (R12-proven, verbatim) -----------------
typedef unsigned long long u64t;

__device__ __forceinline__ void accum_row2(const float* __restrict__ row,
                                           int ti, int tj, u64t acc[8][4]) {
    float4 a0 = *(const float4*)(row + (ti << 3));
    float4 a1 = *(const float4*)(row + (ti << 3) + 4);
    ulonglong2 bq0 = *(const ulonglong2*)(row + (tj << 3));
    ulonglong2 bq1 = *(const ulonglong2*)(row + (tj << 3) + 4);
    u64t bp[4] = {bq0.x, bq0.y, bq1.x, bq1.y};
    float av[8] = {a0.x, a0.y, a0.z, a0.w, a1.x, a1.y, a1.z, a1.w};
#pragma unroll
    for (int a = 0; a < 8; a++) {
        u64t ad;
        asm("mov.b64 %0, {%1, %1};" : "=l"(ad) : "f"(av[a]));
#pragma unroll
        for (int b = 0; b < 4; b++)
            asm("fma.rn.f32x2 %0, %1, %2, %0;" : "+l"(acc[a][b]) : "l"(ad), "l"(bp[b]));
    }
}

__device__ __forceinline__ void flush_acc2(int cls, int ti, int tj, u64t acc[8][4]) {
#pragma unroll
    for (int a = 0; a < 8; a++)
#pragma unroll
        for (int b = 0; b < 4; b++) {
            float lo, hi;
            asm("mov.b64 {%0, %1}, %2;" : "=f"(lo), "=f"(hi) : "l"(acc[a][b]));
            int r = ti * 8 + a, c = tj * 8 + 2 * b;
            atomicAdd(&g_cov[cls][r][c],     lo);
            atomicAdd(&g_cov[cls][r][c + 1], hi);
            acc[a][b] = 0ull;
        }
}

__global__ void __launch_bounds__(GTPB, 2) k_gemm(const float* __restrict__ Z, int M) {
    __shared__ float s_rows[2][BATCH][DD];   // 16 KB, double buffered
    int tid = threadIdx.x;
    int wid = tid >> 5, lane = tid & 31;
    int p0 = blockIdx.x * GCHUNK;
    if (p0 >= M) return;
    int pend = min(p0 + GCHUNK, M);

    int grp = (tid >= 144) ? 1 : 0;
    int id  = tid - grp * 144;
    int ti = -1, tj = -1;
    if (id < 136) {
        int i = 0, rem = id;
        while (rem >= 16 - i) { rem -= 16 - i; i++; }
        ti = i; tj = i + rem;
    }

    u64t acc[8][4];
#pragma unroll
    for (int a = 0; a < 8; a++)
#pragma unroll
        for (int b = 0; b < 4; b++) acc[a][b] = 0ull;

    int cur = 0;
    while (cur < NCLS - 1 && g_class_start[cur + 1] <= p0) cur++;
    int nextb = g_class_start[cur + 1];

    int srow = 2 * wid + (lane >> 4);
    int scol = lane & 15;

    if (wid < 8) {
        int pos = p0 + srow;
        if (pos < pend) {
            int row = g_order[pos];
            const float4* src = (const float4*)(Z + (size_t)row * DD);
            float4* dst = (float4*)s_rows[0][srow];
            dst[scol]      = src[scol];
            dst[scol + 16] = src[scol + 16];
        }
    }
    __syncthreads();

    int ib = 0;
    for (int p = p0; p < pend; p += BATCH, ib ^= 1) {
        int nb = min(BATCH, pend - p);
        if (wid < 8 && p + BATCH < pend) {
            int pos = p + BATCH + srow;
            if (pos < pend) {
                int row = g_order[pos];
                const float4* src = (const float4*)(Z + (size_t)row * DD);
                float4* dst = (float4*)s_rows[ib ^ 1][srow];
                dst[scol]      = src[scol];
                dst[scol + 16] = src[scol + 16];
            }
        }

        if (nb == BATCH && p + BATCH <= nextb) {
            if (ti >= 0) {
#pragma unroll
                for (int k = 0; k < BATCH; k += 2)
                    accum_row2(s_rows[ib][k + grp], ti, tj, acc);
            }
        } else {
            for (int k = 0; k < nb; k++) {
                if (p + k >= nextb && cur < NCLS - 1) {
                    if (ti >= 0) flush_acc2(cur, ti, tj, acc);
                    cur++;
                    while (cur < NCLS - 1 && g_class_start[cur + 1] <= p + k) cur++;
                    nextb = g_class_start[cur + 1];
                }
                if (ti >= 0 && (k & 1) == grp)
                    accum_row2(s_rows[ib][k], ti, tj, acc);
            }
        }
        __syncthreads();
    }
    if (ti >= 0) flush_acc2(cur, ti, tj, acc);
}

// ---------------- K4b: global cov = sum of class covs (proven) --------------
__global__ void k_sumglobal(void) {
    int r = blockIdx.x, c = threadIdx.x;
    float s = 0.0f;
#pragma unroll
    for (int j = 0; j < NCLS; j++) s += g_cov[j][r][c];
    g_cov[NCLS][r][c] = s;
}

// ------- K5: 4x4-TILE Cholesky + fused last-block finalize -------------------
// Tile (R,C), R>=C, owns rows 4R..4R+3 x cols 4C..4C+3. Per step: phase 1
// (rows scale col k, fp64-compensated pivots — identical to proven chain);
// phase 2: tile update via two LDS.128 + 16 FFMA; owner of column k+1
// publishes its raw values. Element update order identical to proven code.
__global__ void __launch_bounds__(CTPB) k_chol_fin(float* __restrict__ out, int M) {
    __shared__ __align__(16) float s_colraw[DD];
    __shared__ __align__(16) float s_col[DD];
    __shared__ float  s_piv[2];
    __shared__ double s_diag[DD];
    __shared__ double s_red[DD];
    __shared__ int    s_last;
    int j = blockIdx.x;                   // 0..31 class, 32 global
    int tid = threadIdx.x;

    bool has = (j == NCLS) || (g_counts[j] > 0);

    if (has) {
        const float (*C)[DD] = g_cov[j];

        // tile assignment: thread t -> tile t; threads 496..511 also own 512..527
        int nt = (tid >= CTPB - 16) ? 2 : 1;
        int tR[2], tC[2];
        float pv[2][4][4];
#pragma unroll
        for (int t = 0; t < 2; t++) {
            int p = (t == 0) ? tid : (CTPB + (tid - (CTPB - 16)));
            if (t >= nt) p = 0;                       // inert duplicate of tile 0
            int R = (int)((sqrtf(8.0f * (float)p + 1.0f) - 1.0f) * 0.5f);
            while (R * (R + 1) / 2 > p) R--;
            while ((R + 1) * (R + 2) / 2 <= p) R++;
            int Cc = p - R * (R + 1) / 2;
            tR[t] = R * 4; tC[t] = Cc * 4;
#pragma unroll
            for (int i2 = 0; i2 < 4; i2++)
#pragma unroll
                for (int j2 = 0; j2 < 4; j2++) {
                    int r = tR[t] + i2, c = tC[t] + j2;
                    int lo = min(r, c), hi = max(r, c);
                    pv[t][i2][j2] = C[lo][hi];
                }
        }
        if (nt == 1) { tC[1] = DD; }                  // never active

        double mydiag = 0.0;
        if (tid < DD) {
            s_colraw[tid] = C[0][tid];
            mydiag = (double)C[tid][tid];
            if (tid == 0) { s_piv[0] = (float)mydiag; s_diag[0] = mydiag; }
        }
        __syncthreads();

        for (int k = 0; k < DD; k++) {
            // phase 1 (proven pivot chain)
            if (tid < DD && tid > k) {
                float inv = rsqrtf(s_piv[k & 1]);
                float lrk = s_colraw[tid] * inv;
                s_col[tid] = lrk;
                mydiag -= (double)lrk * (double)lrk;
                if (tid == k + 1) {
                    s_piv[(k + 1) & 1] = (float)mydiag;
                    s_diag[tid] = mydiag;
                }
            }
            __syncthreads();
            // phase 2: tile rank-1 updates + publish column k+1
#pragma unroll
            for (int t = 0; t < 2; t++) {
                if (tC[t] + 3 > k && tC[t] < DD) {
                    float4 cr = *(const float4*)&s_col[tR[t]];
                    float4 cc = *(const float4*)&s_col[tC[t]];
                    float crv[4] = {cr.x, cr.y, cr.z, cr.w};
                    float ccv[4] = {cc.x, cc.y, cc.z, cc.w};
#pragma unroll
                    for (int j2 = 0; j2 < 4; j2++) {
                        if (tC[t] + j2 > k) {
#pragma unroll
                            for (int i2 = 0; i2 < 4; i2++)
                                pv[t][i2][j2] -= crv[i2] * ccv[j2];
                        }
                    }
                    int jj = k + 1 - tC[t];
                    if (jj >= 0 && jj < 4) {
#pragma unroll
                        for (int i2 = 0; i2 < 4; i2++)
                            if (tR[t] + i2 > k + 1)
                                s_colraw[tR[t] + i2] = pv[t][i2][jj];
                    }
                }
            }
            __syncthreads();
        }

        if (tid < DD) s_red[tid] = log(s_diag[tid]);
        __syncthreads();
        for (int s = DD / 2; s > 0; s >>= 1) {
            if (tid < s) s_red[tid] += s_red[tid + s];
            __syncthreads();
        }
        if (tid == 0) g_logdet[j] = s_red[0];
    } else {
        if (tid == 0) g_logdet[j] = 0.0;
    }

    // last block to finish runs the finalize (proven R13 pattern)
    __syncthreads();
    __threadfence();
    if (tid == 0)
        s_last = (atomicInc(&g_done_c, (unsigned)NCLS) == (unsigned)NCLS) ? 1 : 0;
    __syncthreads();
    if (s_last && tid < 32) {
        double m = (double)M;
        double term = 0.0;
        if (tid < NCLS) {
            int mj = g_counts[tid];
            if (mj > 0) {
                double cj = (double)DD / ((double)mj * 0.01);
                double ld = __ldcg(&g_logdet[tid]);
                term = ((double)DD * log(cj) + ld) * (double)mj / (2.0 * m);
            }
        }
#pragma unroll
        for (int d = 16; d > 0; d >>= 1)
            term += __shfl_down_sync(0xFFFFFFFFu, term, d);
        if (tid == 0) {
            double c = (double)DD / (m * 0.01);
            double expd = ((double)DD * log(c) + __ldcg(&g_logdet[NCLS])) * 0.5;
            out[0] = (float)(term - expd);
        }
    }
}

// ---------------- launch ----------------
extern "C" void kernel_launch(void* const* d_in, const int* in_sizes, int n_in,
                              void* d_out, int out_size) {
    const float* Z     = (const float*)d_in[0];
    const int*   label = (const int*)d_in[1];
    int M = in_sizes[1];
    int nchunk = (M + OCHUNK - 1) / OCHUNK;
    int ggrid  = (M + GCHUNK - 1) / GCHUNK;

    k_hist<<<nchunk, 256>>>(label, M);
    k_scan<<<1, 1024>>>(nchunk);
    k_order<<<nchunk, 256>>>(label, M);
    k_gemm<<<ggrid, GTPB>>>(Z, M);
    k_sumglobal<<<DD, DD>>>();
    k_chol_fin<<<NCLS + 1, CTPB>>>((float*)d_out, M);
}

// round 15
// speedup vs baseline: 1.2005x; 1.0257x over previous
#include <cuda_runtime.h>
#include <math.h>
#include <stdint.h>

// ---------------- problem constants ----------------
#define DD     128          // feature dim
#define NCLS   32           // number of classes
#define OCHUNK 1024         // rows per hist/order chunk
#define GCHUNK 896          // rows per gemm CTA (multiple of BATCH)
#define MAXCHUNK 1024
#define GTPB   288          // gemm threads per block (9 warps)
#define BATCH  16           // rows staged per smem batch
#define NSTAGE 5            // smem ring slots (prefetch distance 3)
#define MAXM   (1 << 19)
#define SCAN_GROUPS 16      // supports nchunk <= 512

// cholesky kernel config
#define CTPB   512

// ---------------- device scratch ----------------
__device__ float  g_cov[NCLS + 1][DD][DD];      // [32] = global (k_sumglobal)
__device__ int    g_chunk_cnt[MAXCHUNK][NCLS];
__device__ int    g_counts[NCLS];
__device__ int    g_class_start[NCLS + 1];
__device__ int    g_order[MAXM];
__device__ double g_logdet[NCLS + 1];
__device__ unsigned int g_done_c;               // self-resetting via atomicInc wrap

// ---------------- K1: per-chunk histogram + zero cov (proven R12) ------------
__global__ void k_hist(const int* __restrict__ label, int M) {
    __shared__ int cnt[NCLS];
    int tid = threadIdx.x, b = blockIdx.x;
    if (tid < NCLS) cnt[tid] = 0;
    __syncthreads();
    int base = b * OCHUNK;
    int end  = min(base + OCHUNK, M);
    for (int r = base + tid; r < end; r += blockDim.x)
        atomicAdd(&cnt[label[r]], 1);
    __syncthreads();
    if (tid < NCLS) g_chunk_cnt[b][tid] = cnt[tid];

    float* cf = &g_cov[0][0][0];
    const int TOT = (NCLS + 1) * DD * DD;
    for (int i = b * blockDim.x + tid; i < TOT; i += gridDim.x * blockDim.x)
        cf[i] = 0.0f;
}

// ------- K2: parallel offsets (proven R12). Warp j = class j. ----------------
__global__ void k_scan(int nchunk) {
    __shared__ int s_tot[NCLS];
    __shared__ int s_start[NCLS + 1];
    int j = threadIdx.x >> 5;
    int l = threadIdx.x & 31;

    int c[SCAN_GROUPS], excl[SCAN_GROUPS];
    int run = 0;
#pragma unroll
    for (int i = 0; i < SCAN_GROUPS; i++) {
        int b = 32 * i + l;
        c[i] = (b < nchunk) ? g_chunk_cnt[b][j] : 0;
        int incl = c[i];
#pragma unroll
        for (int d = 1; d < 32; d <<= 1) {
            int v = __shfl_up_sync(0xFFFFFFFFu, incl, d);
            if (l >= d) incl += v;
        }
        excl[i] = run + (incl - c[i]);
        run += __shfl_sync(0xFFFFFFFFu, incl, 31);
    }
    if (l == 0) s_tot[j] = run;
    __syncthreads();
    if (threadIdx.x == 0) {
        int s = 0;
        for (int jj = 0; jj < NCLS; jj++) { s_start[jj] = s; s += s_tot[jj]; }
        s_start[NCLS] = s;
    }
    __syncthreads();
    if (l == 0) {
        g_counts[j] = s_tot[j];
        g_class_start[j] = s_start[j];
        if (j == 0) g_class_start[NCLS] = s_start[NCLS];
    }
    int base = s_start[j];
#pragma unroll
    for (int i = 0; i < SCAN_GROUPS; i++) {
        int b = 32 * i + l;
        if (b < nchunk) g_chunk_cnt[b][j] = base + excl[i];
    }
}

// ---------------- K3: stable class-sorted order (proven R12) -----------------
__global__ void k_order(const int* __restrict__ label, int M) {
    __shared__ int lbl[OCHUNK];
    int tid = threadIdx.x, b = blockIdx.x;
    int base = b * OCHUNK;
    int n = min(OCHUNK, M - base);
    for (int i = tid; i < n; i += blockDim.x) lbl[i] = label[base + i];
    __syncthreads();
    if (tid < NCLS) {
        int pos = g_chunk_cnt[b][tid];
        for (int r = 0; r < n; r++)
            if (lbl[r] == tid) {
                if (pos >= 0 && pos < MAXM) g_order[pos] = base + r;
                pos++;
            }
    }
}

// ---------------- K4: segmented A^T A — cp.async 5-slot pipeline -------------
typedef unsigned long long u64t;

__device__ __forceinline__ uint32_t smem_u32(const void* p) {
    uint32_t a;
    asm("{ .reg .u64 t; cvta.to.shared.u64 t, %1; cvt.u32.u64 %0, t; }" : "=r"(a) : "l"(p));
    return a;
}

__device__ __forceinline__ void accum_row2(const float* __restrict__ row,
                                           int ti, int tj, u64t acc[8][4]) {
    float4 a0 = *(const float4*)(row + (ti << 3));
    float4 a1 = *(const float4*)(row + (ti << 3) + 4);
    ulonglong2 bq0 = *(const ulonglong2*)(row + (tj << 3));
    ulonglong2 bq1 = *(const ulonglong2*)(row + (tj << 3) + 4);
    u64t bp[4] = {bq0.x, bq0.y, bq1.x, bq1.y};
    float av[8] = {a0.x, a0.y, a0.z, a0.w, a1.x, a1.y, a1.z, a1.w};
#pragma unroll
    for (int a = 0; a < 8; a++) {
        u64t ad;
        asm("mov.b64 %0, {%1, %1};" : "=l"(ad) : "f"(av[a]));
#pragma unroll
        for (int b = 0; b < 4; b++)
            asm("fma.rn.f32x2 %0, %1, %2, %0;" : "+l"(acc[a][b]) : "l"(ad), "l"(bp[b]));
    }
}

__device__ __forceinline__ void flush_acc2(int cls, int ti, int tj, u64t acc[8][4]) {
#pragma unroll
    for (int a = 0; a < 8; a++)
#pragma unroll
        for (int b = 0; b < 4; b++) {
            float lo, hi;
            asm("mov.b64 {%0, %1}, %2;" : "=f"(lo), "=f"(hi) : "l"(acc[a][b]));
            int r = ti * 8 + a, c = tj * 8 + 2 * b;
            atomicAdd(&g_cov[cls][r][c],     lo);
            atomicAdd(&g_cov[cls][r][c + 1], hi);
            acc[a][b] = 0ull;
        }
}

// async-stage one batch into slot: warps 0-7, half-warp h stages row h
__device__ __forceinline__ void stage_async(float* slotbase, const float* __restrict__ Z,
                                            int pbatch, int pend, int wid, int lane) {
    if (wid < 8) {
        int srow = 2 * wid + (lane >> 4);
        int scol = lane & 15;                    // float4 index 0..15
        int pos = pbatch + srow;
        if (pos < pend) {
            int row = g_order[pos];              // half-warp broadcast
            const char* src = (const char*)(Z + (size_t)row * DD) + scol * 16;
            uint32_t dst = smem_u32(slotbase + srow * DD) + scol * 16;
            asm volatile("cp.async.cg.shared.global [%0], [%1], 16;" :: "r"(dst), "l"(src) : "memory");
            asm volatile("cp.async.cg.shared.global [%0], [%1], 16;" :: "r"(dst + 256), "l"(src + 256) : "memory");
        }
    }
}

__global__ void __launch_bounds__(GTPB, 2) k_gemm(const float* __restrict__ Z, int M) {
    extern __shared__ float s_ring[];           // NSTAGE * BATCH * DD floats (40 KB)
    int tid = threadIdx.x;
    int wid = tid >> 5, lane = tid & 31;
    int p0 = blockIdx.x * GCHUNK;
    if (p0 >= M) return;
    int pend = min(p0 + GCHUNK, M);

    int grp = (tid >= 144) ? 1 : 0;
    int id  = tid - grp * 144;
    int ti = -1, tj = -1;
    if (id < 136) {
        int i = 0, rem = id;
        while (rem >= 16 - i) { rem -= 16 - i; i++; }
        ti = i; tj = i + rem;
    }

    u64t acc[8][4];
#pragma unroll
    for (int a = 0; a < 8; a++)
#pragma unroll
        for (int b = 0; b < 4; b++) acc[a][b] = 0ull;

    int cur = 0;
    while (cur < NCLS - 1 && g_class_start[cur + 1] <= p0) cur++;
    int nextb = g_class_start[cur + 1];

    // prologue: stage batches 0,1,2 (3 commit groups; uniform across threads)
#pragma unroll
    for (int s = 0; s < 3; s++) {
        stage_async(s_ring + s * (BATCH * DD), Z, p0 + s * BATCH, pend, wid, lane);
        asm volatile("cp.async.commit_group;" ::: "memory");
    }

    int it = 0;
    for (int p = p0; p < pend; p += BATCH, it++) {
        // stage batch it+3 (possibly empty), always commit (uniform group count)
        stage_async(s_ring + ((it + 3) % NSTAGE) * (BATCH * DD), Z,
                    p + 3 * BATCH, pend, wid, lane);
        asm volatile("cp.async.commit_group;" ::: "memory");
        // committed groups = it+4; <=3 pending => batch it complete
        asm volatile("cp.async.wait_group 3;" ::: "memory");
        __syncthreads();

        const float* sb = s_ring + (it % NSTAGE) * (BATCH * DD);
        int nb = min(BATCH, pend - p);

        if (nb == BATCH && p + BATCH <= nextb) {
            if (ti >= 0) {
#pragma unroll
                for (int k = 0; k < BATCH; k += 2)
                    accum_row2(sb + (k + grp) * DD, ti, tj, acc);
            }
        } else {
            for (int k = 0; k < nb; k++) {
                if (p + k >= nextb && cur < NCLS - 1) {
                    if (ti >= 0) flush_acc2(cur, ti, tj, acc);
                    cur++;
                    while (cur < NCLS - 1 && g_class_start[cur + 1] <= p + k) cur++;
                    nextb = g_class_start[cur + 1];
                }
                if (ti >= 0 && (k & 1) == grp)
                    accum_row2(sb + k * DD, ti, tj, acc);
            }
        }
    }
    if (ti >= 0) flush_acc2(cur, ti, tj, acc);
}

// ---------------- K4b: global cov = sum of class covs (proven) --------------
__global__ void k_sumglobal(void) {
    int r = blockIdx.x, c = threadIdx.x;
    float s = 0.0f;
#pragma unroll
    for (int j = 0; j < NCLS; j++) s += g_cov[j][r][c];
    g_cov[NCLS][r][c] = s;
}

// ------- K5: 4x4-TILE Cholesky + fused last-block finalize (R14-proven) ------
__global__ void __launch_bounds__(CTPB) k_chol_fin(float* __restrict__ out, int M) {
    __shared__ __align__(16) float s_colraw[DD];
    __shared__ __align__(16) float s_col[DD];
    __shared__ float  s_piv[2];
    __shared__ double s_diag[DD];
    __shared__ double s_red[DD];
    __shared__ int    s_last;
    int j = blockIdx.x;                   // 0..31 class, 32 global
    int tid = threadIdx.x;

    bool has = (j == NCLS) || (g_counts[j] > 0);

    if (has) {
        const float (*C)[DD] = g_cov[j];

        int nt = (tid >= CTPB - 16) ? 2 : 1;
        int tR[2], tC[2];
        float pv[2][4][4];
#pragma unroll
        for (int t = 0; t < 2; t++) {
            int p = (t == 0) ? tid : (CTPB + (tid - (CTPB - 16)));
            if (t >= nt) p = 0;
            int R = (int)((sqrtf(8.0f * (float)p + 1.0f) - 1.0f) * 0.5f);
            while (R * (R + 1) / 2 > p) R--;
            while ((R + 1) * (R + 2) / 2 <= p) R++;
            int Cc = p - R * (R + 1) / 2;
            tR[t] = R * 4; tC[t] = Cc * 4;
#pragma unroll
            for (int i2 = 0; i2 < 4; i2++)
#pragma unroll
                for (int j2 = 0; j2 < 4; j2++) {
                    int r = tR[t] + i2, c = tC[t] + j2;
                    int lo = min(r, c), hi = max(r, c);
                    pv[t][i2][j2] = C[lo][hi];
                }
        }
        if (nt == 1) { tC[1] = DD; }

        double mydiag = 0.0;
        if (tid < DD) {
            s_colraw[tid] = C[0][tid];
            mydiag = (double)C[tid][tid];
            if (tid == 0) { s_piv[0] = (float)mydiag; s_diag[0] = mydiag; }
        }
        __syncthreads();

        for (int k = 0; k < DD; k++) {
            if (tid < DD && tid > k) {
                float inv = rsqrtf(s_piv[k & 1]);
                float lrk = s_colraw[tid] * inv;
                s_col[tid] = lrk;
                mydiag -= (double)lrk * (double)lrk;
                if (tid == k + 1) {
                    s_piv[(k + 1) & 1] = (float)mydiag;
                    s_diag[tid] = mydiag;
                }
            }
            __syncthreads();
#pragma unroll
            for (int t = 0; t < 2; t++) {
                if (tC[t] + 3 > k && tC[t] < DD) {
                    float4 cr = *(const float4*)&s_col[tR[t]];
                    float4 cc = *(const float4*)&s_col[tC[t]];
                    float crv[4] = {cr.x, cr.y, cr.z, cr.w};
                    float ccv[4] = {cc.x, cc.y, cc.z, cc.w};
#pragma unroll
                    for (int j2 = 0; j2 < 4; j2++) {
                        if (tC[t] + j2 > k) {
#pragma unroll
                            for (int i2 = 0; i2 < 4; i2++)
                                pv[t][i2][j2] -= crv[i2] * ccv[j2];
                        }
                    }
                    int jj = k + 1 - tC[t];
                    if (jj >= 0 && jj < 4) {
#pragma unroll
                        for (int i2 = 0; i2 < 4; i2++)
                            if (tR[t] + i2 > k + 1)
                                s_colraw[tR[t] + i2] = pv[t][i2][jj];
                    }
                }
            }
            __syncthreads();
        }

        if (tid < DD) s_red[tid] = log(s_diag[tid]);
        __syncthreads();
        for (int s = DD / 2; s > 0; s >>= 1) {
            if (tid < s) s_red[tid] += s_red[tid + s];
            __syncthreads();
        }
        if (tid == 0) g_logdet[j] = s_red[0];
    } else {
        if (tid == 0) g_logdet[j] = 0.0;
    }

    __syncthreads();
    __threadfence();
    if (tid == 0)
        s_last = (atomicInc(&g_done_c, (unsigned)NCLS) == (unsigned)NCLS) ? 1 : 0;
    __syncthreads();
    if (s_last && tid < 32) {
        double m = (double)M;
        double term = 0.0;
        if (tid < NCLS) {
            int mj = g_counts[tid];
            if (mj > 0) {
                double cj = (double)DD / ((double)mj * 0.01);
                double ld = __ldcg(&g_logdet[tid]);
                term = ((double)DD * log(cj) + ld) * (double)mj / (2.0 * m);
            }
        }
#pragma unroll
        for (int d = 16; d > 0; d >>= 1)
            term += __shfl_down_sync(0xFFFFFFFFu, term, d);
        if (tid == 0) {
            double c = (double)DD / (m * 0.01);
            double expd = ((double)DD * log(c) + __ldcg(&g_logdet[NCLS])) * 0.5;
            out[0] = (float)(term - expd);
        }
    }
}

// ---------------- launch ----------------
extern "C" void kernel_launch(void* const* d_in, const int* in_sizes, int n_in,
                              void* d_out, int out_size) {
    const float* Z     = (const float*)d_in[0];
    const int*   label = (const int*)d_in[1];
    int M = in_sizes[1];
    int nchunk = (M + OCHUNK - 1) / OCHUNK;
    int ggrid  = (M + GCHUNK - 1) / GCHUNK;
    const int GSMEM = NSTAGE * BATCH * DD * (int)sizeof(float);   // 40960 B

    cudaFuncSetAttribute(k_gemm, cudaFuncAttributeMaxDynamicSharedMemorySize, GSMEM);

    k_hist<<<nchunk, 256>>>(label, M);
    k_scan<<<1, 1024>>>(nchunk);
    k_order<<<nchunk, 256>>>(label, M);
    k_gemm<<<ggrid, GTPB, GSMEM>>>(Z, M);
    k_sumglobal<<<DD, DD>>>();
    k_chol_fin<<<NCLS + 1, CTPB>>>((float*)d_out, M);
}